// round 13
// baseline (speedup 1.0000x reference)
#include <cuda_runtime.h>
#include <cuda_fp16.h>
#include <cstdint>

// ---------------- problem constants ----------------
#define HD   64
#define NHEADS 4
#define NMAX 50000
#define EMAX 400000
#define EEMAX (EMAX + NMAX)
#define FMAX 256

// ---------------- device scratch ----------------
__device__ __half g_h16[(size_t)NMAX * FMAX];  // gemm output (fp16, agg input)
__device__ float g_acc[(size_t)NMAX * FMAX];   // aggregation output
__device__ float g_res[(size_t)NMAX * FMAX];   // residual (bn1 out)
__device__ __half g_ah[(size_t)NMAX * FMAX];   // A hi (all layers)
__device__ __half g_al[(size_t)NMAX * FMAX];   // A lo (layer-3 input only)
__device__ __half g_w1h[FMAX * FMAX];
__device__ __half g_w2h[FMAX * FMAX];
__device__ __half g_w3h[HD * FMAX];
__device__ __half g_w3l[HD * FMAX];
__device__ float g_als[NMAX * NHEADS];
__device__ float g_ald[NMAX * NHEADS];
__device__ float g_sumsA[FMAX];
__device__ float g_sumsqA[FMAX];
__device__ float g_sumsB[FMAX];
__device__ float g_sumsqB[FMAX];
// CSR
__device__ int g_counts[NMAX + 1];
__device__ int g_start[NMAX + 1];
__device__ int g_woff[NMAX];
__device__ int g_bsums[256];
__device__ int g_csr_src[EEMAX];

// ---------------- PTX helpers ----------------
__device__ __forceinline__ uint32_t smem_u32(const void* p) {
    uint32_t a;
    asm("{ .reg .u64 t; cvta.to.shared.u64 t, %1; cvt.u32.u64 %0, t; }" : "=r"(a) : "l"(p));
    return a;
}
__device__ __forceinline__ void cp16z(uint32_t dst, const void* src, uint32_t nbytes) {
    asm volatile("cp.async.cg.shared.global [%0], [%1], 16, %2;"
                 :: "r"(dst), "l"(src), "r"(nbytes));
}
#define CP_COMMIT() asm volatile("cp.async.commit_group;" ::: "memory")
#define LDMATRIX_X4(R0, R1, R2, R3, ADDR)                                   \
    asm volatile("ldmatrix.sync.aligned.m8n8.x4.shared.b16 {%0,%1,%2,%3}, [%4];" \
                 : "=r"(R0), "=r"(R1), "=r"(R2), "=r"(R3) : "r"(ADDR))
#define MMA_FP16(C, A, B)                                                   \
    asm volatile("mma.sync.aligned.m16n8k16.row.col.f32.f16.f16.f32 "      \
                 "{%0,%1,%2,%3}, {%4,%5,%6,%7}, {%8,%9}, {%0,%1,%2,%3};"    \
                 : "+f"((C)[0]), "+f"((C)[1]), "+f"((C)[2]), "+f"((C)[3])   \
                 : "r"((A)[0]), "r"((A)[1]), "r"((A)[2]), "r"((A)[3]),      \
                   "r"((B)[0]), "r"((B)[1]))

__device__ __forceinline__ float expw(float v) {
    v = v > 0.f ? v : 0.2f * v;
    return __expf(v);
}

// ---------------- fp32 -> fp16 splits ----------------
__global__ void split_hilo_kernel(const float4* __restrict__ in,
                                  __half2* __restrict__ hi,
                                  __half2* __restrict__ lo, int n4) {
    int i = blockIdx.x * blockDim.x + threadIdx.x;
    if (i >= n4) return;
    float4 v = in[i];
    __half h0 = __float2half(v.x), h1 = __float2half(v.y);
    __half h2 = __float2half(v.z), h3 = __float2half(v.w);
    hi[i * 2 + 0] = __half2(h0, h1);
    hi[i * 2 + 1] = __half2(h2, h3);
    lo[i * 2 + 0] = __half2(__float2half(v.x - __half2float(h0)),
                            __float2half(v.y - __half2float(h1)));
    lo[i * 2 + 1] = __half2(__float2half(v.z - __half2float(h2)),
                            __float2half(v.w - __half2float(h3)));
}
__global__ void split_hi_kernel(const float4* __restrict__ in,
                                __half2* __restrict__ hi, int n4) {
    int i = blockIdx.x * blockDim.x + threadIdx.x;
    if (i >= n4) return;
    float4 v = in[i];
    hi[i * 2 + 0] = __half2(__float2half(v.x), __float2half(v.y));
    hi[i * 2 + 1] = __half2(__float2half(v.z), __float2half(v.w));
}

// ---------------- HMMA GEMM (fp16) + fused logits; fp16 C store ----------------
template<int NTILE, int TERMS>
__global__ void __launch_bounds__(256) gemm_mma(
    const __half* __restrict__ Ah, const __half* __restrict__ Al,
    const __half* __restrict__ Wh, const __half* __restrict__ Wl,
    __half* __restrict__ C16, int Nrows, int K, int NOUT,
    const float* __restrict__ a_s, const float* __restrict__ a_d,
    float* __restrict__ als, float* __restrict__ ald) {
    constexpr int RS = 40;
    constexpr int MT = (NTILE == 128) ? 2 : 1;
    constexpr int WN = NTILE / 64;
    constexpr int HH = (NTILE == 128) ? 4 : 1;
    constexpr int NA = (TERMS == 3) ? 2 : 1;
    constexpr int NW = (TERMS >= 2) ? 2 : 1;
    constexpr int A_BYTES = 128 * RS * 2;
    constexpr int W_BYTES = NTILE * RS * 2;
    constexpr int STAGE = NA * A_BYTES + NW * W_BYTES;
    extern __shared__ char dsm[];
    const uint32_t sbase = smem_u32(dsm);
    const int tid = threadIdx.x, lane = tid & 31, wid = tid >> 5;
    const int wm = wid / WN, wn = wid % WN;
    const int row0 = blockIdx.x * 128, col0 = blockIdx.y * NTILE;

    const int a_row  = ((lane >> 3) & 1) * 8 + (lane & 7);
    const int a_koff = ((lane >> 4) & 1) * 8;
    const int b_row  = ((lane >> 4) & 1) * 8 + (lane & 7);
    const int b_koff = ((lane >> 3) & 1) * 8;
    const uint32_t a_off = (uint32_t)(((wm * 16 * MT + a_row) * RS + a_koff) * 2);
    const uint32_t b_off = (uint32_t)(((wn * 64 + b_row) * RS + b_koff) * 2);

    float acc[MT][8][4];
    #pragma unroll
    for (int mt = 0; mt < MT; mt++)
        #pragma unroll
        for (int nt = 0; nt < 8; nt++)
            #pragma unroll
            for (int j = 0; j < 4; j++) acc[mt][nt][j] = 0.f;

    const int nchunks = K >> 5;

    auto issue_chunk = [&](int ck) {
        const int st = ck & 1;
        const uint32_t ah_s = sbase + st * STAGE;
        const uint32_t al_s = ah_s + A_BYTES;
        const uint32_t wh_s = ah_s + NA * A_BYTES;
        const uint32_t wl_s = wh_s + W_BYTES;
        const int k0 = ck << 5;
        #pragma unroll 2
        for (int i = tid; i < 512; i += 256) {
            int r = i >> 2, c16 = i & 3;
            int gr = row0 + r;
            uint32_t nb = (gr < Nrows) ? 16u : 0u;
            if (gr >= Nrows) gr = Nrows - 1;
            uint32_t dof = (uint32_t)(r * RS + c16 * 8) * 2;
            cp16z(ah_s + dof, (const char*)(Ah + (size_t)gr * K + k0) + c16 * 16, nb);
            if (NA == 2)
                cp16z(al_s + dof, (const char*)(Al + (size_t)gr * K + k0) + c16 * 16, nb);
        }
        #pragma unroll 2
        for (int i = tid; i < NTILE * 4; i += 256) {
            int r = i >> 2, c16 = i & 3;
            uint32_t dof = (uint32_t)(r * RS + c16 * 8) * 2;
            cp16z(wh_s + dof, (const char*)(Wh + (size_t)(col0 + r) * K + k0) + c16 * 16, 16u);
            if (NW == 2)
                cp16z(wl_s + dof, (const char*)(Wl + (size_t)(col0 + r) * K + k0) + c16 * 16, 16u);
        }
        CP_COMMIT();
    };

    issue_chunk(0);
    for (int ck = 0; ck < nchunks; ck++) {
        if (ck + 1 < nchunks) {
            issue_chunk(ck + 1);
            asm volatile("cp.async.wait_group 1;" ::: "memory");
        } else {
            asm volatile("cp.async.wait_group 0;" ::: "memory");
        }
        __syncthreads();
        const int st = ck & 1;
        const uint32_t ahb = sbase + st * STAGE;
        const uint32_t alb = ahb + A_BYTES;
        const uint32_t whb = ahb + NA * A_BYTES;
        const uint32_t wlb = whb + W_BYTES;
        #pragma unroll
        for (int kk = 0; kk < 32; kk += 16) {
            uint32_t ah_f[MT][4], al_f[MT][4];
            #pragma unroll
            for (int mt = 0; mt < MT; mt++) {
                uint32_t o = a_off + (uint32_t)((mt * 16 * RS + kk) * 2);
                LDMATRIX_X4(ah_f[mt][0], ah_f[mt][1], ah_f[mt][2], ah_f[mt][3], ahb + o);
                if (NA == 2)
                    LDMATRIX_X4(al_f[mt][0], al_f[mt][1], al_f[mt][2], al_f[mt][3], alb + o);
            }
            uint32_t bh_f[8][2], bl_f[8][2];
            #pragma unroll
            for (int nt16 = 0; nt16 < 4; nt16++) {
                uint32_t o = b_off + (uint32_t)((nt16 * 16 * RS + kk) * 2);
                uint32_t r0, r1, r2, r3;
                LDMATRIX_X4(r0, r1, r2, r3, whb + o);
                bh_f[nt16 * 2 + 0][0] = r0; bh_f[nt16 * 2 + 0][1] = r1;
                bh_f[nt16 * 2 + 1][0] = r2; bh_f[nt16 * 2 + 1][1] = r3;
                if (NW == 2) {
                    LDMATRIX_X4(r0, r1, r2, r3, wlb + o);
                    bl_f[nt16 * 2 + 0][0] = r0; bl_f[nt16 * 2 + 0][1] = r1;
                    bl_f[nt16 * 2 + 1][0] = r2; bl_f[nt16 * 2 + 1][1] = r3;
                }
            }
            #pragma unroll
            for (int mt = 0; mt < MT; mt++)
                #pragma unroll
                for (int nt = 0; nt < 8; nt++) {
                    MMA_FP16(acc[mt][nt], ah_f[mt], bh_f[nt]);
                    if (TERMS >= 2)
                        MMA_FP16(acc[mt][nt], ah_f[mt], bl_f[nt]);
                    if (TERMS == 3)
                        MMA_FP16(acc[mt][nt], al_f[mt], bh_f[nt]);
                }
        }
        __syncthreads();
    }

    // ---- store C (fp16) ----
    #pragma unroll
    for (int mt = 0; mt < MT; mt++) {
        int mrow = row0 + wm * 16 * MT + mt * 16 + (lane >> 2);
        #pragma unroll
        for (int nt = 0; nt < 8; nt++) {
            int ncol = col0 + wn * 64 + nt * 8 + (lane & 3) * 2;
            __half2 p01 = __floats2half2_rn(acc[mt][nt][0], acc[mt][nt][1]);
            __half2 p23 = __floats2half2_rn(acc[mt][nt][2], acc[mt][nt][3]);
            if (mrow < Nrows)
                *(__half2*)&C16[(size_t)mrow * NOUT + ncol] = p01;
            if (mrow + 8 < Nrows)
                *(__half2*)&C16[(size_t)(mrow + 8) * NOUT + ncol] = p23;
        }
    }

    // ---- fused logits (from fp32 accumulators) ----
    const int hd = blockIdx.y * WN + wn;
    const float* avs = a_s + hd * HD;
    const float* avd = a_d + hd * HD;
    float as_v[16], ad_v[16];
    #pragma unroll
    for (int nt = 0; nt < 8; nt++) {
        int c = nt * 8 + (lane & 3) * 2;
        as_v[nt * 2 + 0] = avs[c];     as_v[nt * 2 + 1] = avs[c + 1];
        ad_v[nt * 2 + 0] = avd[c];     ad_v[nt * 2 + 1] = avd[c + 1];
    }
    #pragma unroll
    for (int mt = 0; mt < MT; mt++) {
        #pragma unroll
        for (int rr = 0; rr < 2; rr++) {
            float ds = 0.f, dd = 0.f;
            #pragma unroll
            for (int nt = 0; nt < 8; nt++) {
                float v0 = acc[mt][nt][rr * 2 + 0], v1 = acc[mt][nt][rr * 2 + 1];
                ds += v0 * as_v[nt * 2] + v1 * as_v[nt * 2 + 1];
                dd += v0 * ad_v[nt * 2] + v1 * ad_v[nt * 2 + 1];
            }
            ds += __shfl_xor_sync(0xffffffff, ds, 1);
            ds += __shfl_xor_sync(0xffffffff, ds, 2);
            dd += __shfl_xor_sync(0xffffffff, dd, 1);
            dd += __shfl_xor_sync(0xffffffff, dd, 2);
            int row = row0 + wm * 16 * MT + mt * 16 + rr * 8 + (lane >> 2);
            if ((lane & 3) == 0 && row < Nrows) {
                als[row * HH + hd] = ds;
                ald[row * HH + hd] = dd;
            }
        }
    }
}

// ---------------- CSR build ----------------
__global__ void zero_int_kernel(int* __restrict__ p, int n) {
    int i = blockIdx.x * blockDim.x + threadIdx.x;
    if (i < n) p[i] = 0;
}
__global__ void count_kernel(const int* __restrict__ ei, int E, int N, int* __restrict__ cnt) {
    int e = blockIdx.x * blockDim.x + threadIdx.x;
    int EE = E + N;
    if (e >= EE) return;
    int d = (e < E) ? ei[E + e] : e - E;
    atomicAdd(&cnt[d], 1);
}
__global__ void scan_block_kernel(const int* __restrict__ cnt, int* __restrict__ excl,
                                  int* __restrict__ bsums, int N) {
    __shared__ int sh[256];
    int tid = threadIdx.x;
    int i = blockIdx.x * 256 + tid;
    int v = (i < N) ? cnt[i] : 0;
    sh[tid] = v;
    __syncthreads();
    #pragma unroll
    for (int off = 1; off < 256; off <<= 1) {
        int t = (tid >= off) ? sh[tid - off] : 0;
        __syncthreads();
        sh[tid] += t;
        __syncthreads();
    }
    if (i < N) excl[i] = sh[tid] - v;
    if (tid == 255) bsums[blockIdx.x] = sh[255];
}
__global__ void scan_sums_kernel(int* __restrict__ bsums, int nb) {
    __shared__ int sh[256];
    int tid = threadIdx.x;
    int v = (tid < nb) ? bsums[tid] : 0;
    sh[tid] = v;
    __syncthreads();
    #pragma unroll
    for (int off = 1; off < 256; off <<= 1) {
        int t = (tid >= off) ? sh[tid - off] : 0;
        __syncthreads();
        sh[tid] += t;
        __syncthreads();
    }
    if (tid < nb) bsums[tid] = sh[tid] - v;
}
__global__ void add_offsets_kernel(int* __restrict__ excl, const int* __restrict__ bsums,
                                   int* __restrict__ woff, int N, int EE) {
    int i = blockIdx.x * 256 + threadIdx.x;
    if (i < N) {
        int v = excl[i] + bsums[blockIdx.x];
        excl[i] = v;
        woff[i] = v;
    }
    if (blockIdx.x == 0 && threadIdx.x == 0) excl[N] = EE;
}
__global__ void fill_kernel(const int* __restrict__ ei, int E, int N,
                            int* __restrict__ woff, int* __restrict__ csr_src) {
    int e = blockIdx.x * blockDim.x + threadIdx.x;
    int EE = E + N;
    if (e >= EE) return;
    int s, d;
    if (e < E) { s = ei[e]; d = ei[E + e]; }
    else       { s = d = e - E; }
    int pos = atomicAdd(&woff[d], 1);
    csr_src[pos] = s;
}

// ---------------- CSR aggregation, H=4 (fp16 h, 4x unroll) ----------------
__global__ void __launch_bounds__(256) agg4_kernel(
    const int* __restrict__ start, const int* __restrict__ csr_src,
    const float* __restrict__ als, const float* __restrict__ ald,
    const __half* __restrict__ h16, const float* __restrict__ bias,
    float* __restrict__ out, int N,
    float* __restrict__ sums, float* __restrict__ sumsq) {
    __shared__ float s_s[256], s_q[256];
    int tid = threadIdx.x, lane = tid & 31, wid = tid >> 5;
    s_s[tid] = 0.f; s_q[tid] = 0.f;
    __syncthreads();
    int d = blockIdx.x * 4 + (wid >> 1);
    int half = wid & 1;
    if (d < N) {
        const float2* als2 = (const float2*)als;
        float2 aldv = ((const float2*)ald)[d * 2 + half];
        float den0 = 0.f, den1 = 0.f;
        float4 acc = make_float4(0.f, 0.f, 0.f, 0.f);
        const uint2* h4 = (const uint2*)h16;
        int c4 = half * 32 + lane;
        int j0 = start[d], j1 = start[d + 1];
        int j = j0;
        for (; j + 4 <= j1; j += 4) {
            int s0 = csr_src[j],     s1 = csr_src[j + 1];
            int s2 = csr_src[j + 2], s3 = csr_src[j + 3];
            float2 a0 = als2[s0 * 2 + half], a1 = als2[s1 * 2 + half];
            float2 a2 = als2[s2 * 2 + half], a3 = als2[s3 * 2 + half];
            uint2 u0 = h4[(size_t)s0 * 64 + c4];
            uint2 u1 = h4[(size_t)s1 * 64 + c4];
            uint2 u2 = h4[(size_t)s2 * 64 + c4];
            uint2 u3 = h4[(size_t)s3 * 64 + c4];
            float e00 = expw(a0.x + aldv.x), e01 = expw(a0.y + aldv.y);
            float e10 = expw(a1.x + aldv.x), e11 = expw(a1.y + aldv.y);
            float e20 = expw(a2.x + aldv.x), e21 = expw(a2.y + aldv.y);
            float e30 = expw(a3.x + aldv.x), e31 = expw(a3.y + aldv.y);
            den0 += e00 + e10 + e20 + e30;
            den1 += e01 + e11 + e21 + e31;
            float w0 = (lane < 16) ? e00 : e01;
            float w1 = (lane < 16) ? e10 : e11;
            float w2 = (lane < 16) ? e20 : e21;
            float w3 = (lane < 16) ? e30 : e31;
            float2 v0a = __half22float2(*(__half2*)&u0.x);
            float2 v0b = __half22float2(*(__half2*)&u0.y);
            float2 v1a = __half22float2(*(__half2*)&u1.x);
            float2 v1b = __half22float2(*(__half2*)&u1.y);
            float2 v2a = __half22float2(*(__half2*)&u2.x);
            float2 v2b = __half22float2(*(__half2*)&u2.y);
            float2 v3a = __half22float2(*(__half2*)&u3.x);
            float2 v3b = __half22float2(*(__half2*)&u3.y);
            acc.x += w0 * v0a.x + w1 * v1a.x + w2 * v2a.x + w3 * v3a.x;
            acc.y += w0 * v0a.y + w1 * v1a.y + w2 * v2a.y + w3 * v3a.y;
            acc.z += w0 * v0b.x + w1 * v1b.x + w2 * v2b.x + w3 * v3b.x;
            acc.w += w0 * v0b.y + w1 * v1b.y + w2 * v2b.y + w3 * v3b.y;
        }
        for (; j < j1; j++) {
            int s0 = csr_src[j];
            float2 a0 = als2[s0 * 2 + half];
            uint2 u0 = h4[(size_t)s0 * 64 + c4];
            float2 v0a = __half22float2(*(__half2*)&u0.x);
            float2 v0b = __half22float2(*(__half2*)&u0.y);
            float e00 = expw(a0.x + aldv.x), e01 = expw(a0.y + aldv.y);
            den0 += e00;
            den1 += e01;
            float w0 = (lane < 16) ? e00 : e01;
            acc.x += w0 * v0a.x; acc.y += w0 * v0a.y;
            acc.z += w0 * v0b.x; acc.w += w0 * v0b.y;
        }
        float inv = 1.f / ((lane < 16) ? den0 : den1);
        float4 bb = ((const float4*)bias)[c4];
        float4 r = make_float4(acc.x * inv + bb.x, acc.y * inv + bb.y,
                               acc.z * inv + bb.z, acc.w * inv + bb.w);
        ((float4*)(out + (size_t)d * 256))[c4] = r;
        int f = c4 * 4;
        atomicAdd(&s_s[f + 0], r.x); atomicAdd(&s_q[f + 0], r.x * r.x);
        atomicAdd(&s_s[f + 1], r.y); atomicAdd(&s_q[f + 1], r.y * r.y);
        atomicAdd(&s_s[f + 2], r.z); atomicAdd(&s_q[f + 2], r.z * r.z);
        atomicAdd(&s_s[f + 3], r.w); atomicAdd(&s_q[f + 3], r.w * r.w);
    }
    __syncthreads();
    atomicAdd(&sums[tid], s_s[tid]);
    atomicAdd(&sumsq[tid], s_q[tid]);
}

// ---------------- CSR aggregation, H=1 (F=64, fp16 h, 4x unroll) ----------------
__global__ void __launch_bounds__(256) agg1_kernel(
    const int* __restrict__ start, const int* __restrict__ csr_src,
    const float* __restrict__ als, const float* __restrict__ ald,
    const __half* __restrict__ h16, const float* __restrict__ bias,
    float* __restrict__ out, int N) {
    int tid = threadIdx.x, lane = tid & 31, wid = tid >> 5;
    int d = blockIdx.x * 8 + wid;
    if (d >= N) return;
    float aldv = ald[d];
    float den = 0.f;
    float2 acc = make_float2(0.f, 0.f);
    const __half2* h2 = (const __half2*)h16;
    int j0 = start[d], j1 = start[d + 1];
    int j = j0;
    for (; j + 4 <= j1; j += 4) {
        int s0 = csr_src[j],     s1 = csr_src[j + 1];
        int s2 = csr_src[j + 2], s3 = csr_src[j + 3];
        float a0 = als[s0], a1 = als[s1], a2 = als[s2], a3 = als[s3];
        float2 v0 = __half22float2(h2[(size_t)s0 * 32 + lane]);
        float2 v1 = __half22float2(h2[(size_t)s1 * 32 + lane]);
        float2 v2 = __half22float2(h2[(size_t)s2 * 32 + lane]);
        float2 v3 = __half22float2(h2[(size_t)s3 * 32 + lane]);
        float e0 = expw(a0 + aldv), e1 = expw(a1 + aldv);
        float e2 = expw(a2 + aldv), e3 = expw(a3 + aldv);
        den += e0 + e1 + e2 + e3;
        acc.x += e0 * v0.x + e1 * v1.x + e2 * v2.x + e3 * v3.x;
        acc.y += e0 * v0.y + e1 * v1.y + e2 * v2.y + e3 * v3.y;
    }
    for (; j < j1; j++) {
        int s0 = csr_src[j];
        float2 v0 = __half22float2(h2[(size_t)s0 * 32 + lane]);
        float e0 = expw(als[s0] + aldv);
        den += e0;
        acc.x += e0 * v0.x;
        acc.y += e0 * v0.y;
    }
    float inv = 1.f / den;
    float2 bb = ((const float2*)bias)[lane];
    ((float2*)(out + (size_t)d * 64))[lane] = make_float2(acc.x * inv + bb.x, acc.y * inv + bb.y);
}

__global__ void zero_stats2_kernel(float* __restrict__ sA, float* __restrict__ qA,
                                   float* __restrict__ sB, float* __restrict__ qB) {
    sA[threadIdx.x] = 0.f; qA[threadIdx.x] = 0.f;
    sB[threadIdx.x] = 0.f; qB[threadIdx.x] = 0.f;
}

// ---------------- BN + leakyReLU (+res) fused with fp16 split ----------------
__global__ void bn_split_kernel(const float4* __restrict__ x, const float4* __restrict__ res_in,
                                const float4* __restrict__ gamma4, const float4* __restrict__ beta4,
                                const float4* __restrict__ sums4, const float4* __restrict__ sumsq4,
                                float invn, int n4, float4* __restrict__ res_out,
                                __half2* __restrict__ hi, __half2* __restrict__ lo) {
    int i = blockIdx.x * blockDim.x + threadIdx.x;
    if (i >= n4) return;
    int f4 = i & 63;
    float4 xv = x[i], g = gamma4[f4], b = beta4[f4], s = sums4[f4], q = sumsq4[f4];
    float4 v;
    {
        float mu = s.x * invn, var = q.x * invn - mu * mu;
        v.x = g.x * (xv.x - mu) * rsqrtf(var + 1e-5f) + b.x;
        mu = s.y * invn; var = q.y * invn - mu * mu;
        v.y = g.y * (xv.y - mu) * rsqrtf(var + 1e-5f) + b.y;
        mu = s.z * invn; var = q.z * invn - mu * mu;
        v.z = g.z * (xv.z - mu) * rsqrtf(var + 1e-5f) + b.z;
        mu = s.w * invn; var = q.w * invn - mu * mu;
        v.w = g.w * (xv.w - mu) * rsqrtf(var + 1e-5f) + b.w;
    }
    v.x = v.x > 0.f ? v.x : 0.01f * v.x;
    v.y = v.y > 0.f ? v.y : 0.01f * v.y;
    v.z = v.z > 0.f ? v.z : 0.01f * v.z;
    v.w = v.w > 0.f ? v.w : 0.01f * v.w;
    if (res_in) {
        float4 r = res_in[i];
        v.x += r.x; v.y += r.y; v.z += r.z; v.w += r.w;
    }
    if (res_out) res_out[i] = v;
    __half h0 = __float2half(v.x), h1 = __float2half(v.y);
    __half h2 = __float2half(v.z), h3 = __float2half(v.w);
    hi[i * 2 + 0] = __half2(h0, h1);
    hi[i * 2 + 1] = __half2(h2, h3);
    if (lo) {
        lo[i * 2 + 0] = __half2(__float2half(v.x - __half2float(h0)),
                                __float2half(v.y - __half2float(h1)));
        lo[i * 2 + 1] = __half2(__float2half(v.z - __half2float(h2)),
                                __float2half(v.w - __half2float(h3)));
    }
}

// ---------------- host ----------------
extern "C" void kernel_launch(void* const* d_in, const int* in_sizes, int n_in,
                              void* d_out, int out_size) {
    const float* x     = (const float*)d_in[0];
    const int*   ei    = (const int*)d_in[1];
    const float* W1    = (const float*)d_in[2];
    const float* a1s   = (const float*)d_in[3];
    const float* a1d   = (const float*)d_in[4];
    const float* b1    = (const float*)d_in[5];
    const float* W2    = (const float*)d_in[6];
    const float* a2s   = (const float*)d_in[7];
    const float* a2d   = (const float*)d_in[8];
    const float* b2    = (const float*)d_in[9];
    const float* W3    = (const float*)d_in[10];
    const float* a3s   = (const float*)d_in[11];
    const float* a3d   = (const float*)d_in[12];
    const float* b3    = (const float*)d_in[13];
    const float* gamma = (const float*)d_in[14];
    const float* beta  = (const float*)d_in[15];
    float* out = (float*)d_out;

    int N = in_sizes[0] / (2 * HD);
    int E = in_sizes[1] / 2;
    int EE = E + N;

    float *acc, *res, *als, *ald, *sumsA, *sumsqA, *sumsB, *sumsqB;
    __half *h16, *ah, *al, *w1h, *w2h, *w3h, *w3l;
    int *counts, *start, *woff, *bsums, *csr_src;
    cudaGetSymbolAddress((void**)&h16,     g_h16);
    cudaGetSymbolAddress((void**)&acc,     g_acc);
    cudaGetSymbolAddress((void**)&res,     g_res);
    cudaGetSymbolAddress((void**)&ah,      g_ah);
    cudaGetSymbolAddress((void**)&al,      g_al);
    cudaGetSymbolAddress((void**)&w1h,     g_w1h);
    cudaGetSymbolAddress((void**)&w2h,     g_w2h);
    cudaGetSymbolAddress((void**)&w3h,     g_w3h);
    cudaGetSymbolAddress((void**)&w3l,     g_w3l);
    cudaGetSymbolAddress((void**)&als,     g_als);
    cudaGetSymbolAddress((void**)&ald,     g_ald);
    cudaGetSymbolAddress((void**)&sumsA,   g_sumsA);
    cudaGetSymbolAddress((void**)&sumsqA,  g_sumsqA);
    cudaGetSymbolAddress((void**)&sumsB,   g_sumsB);
    cudaGetSymbolAddress((void**)&sumsqB,  g_sumsqB);
    cudaGetSymbolAddress((void**)&counts,  g_counts);
    cudaGetSymbolAddress((void**)&start,   g_start);
    cudaGetSymbolAddress((void**)&woff,    g_woff);
    cudaGetSymbolAddress((void**)&bsums,   g_bsums);
    cudaGetSymbolAddress((void**)&csr_src, g_csr_src);

    cudaFuncSetAttribute((const void*)gemm_mma<128, 1>,
                         cudaFuncAttributeMaxDynamicSharedMemorySize, 40960);
    cudaFuncSetAttribute((const void*)gemm_mma<64, 3>,
                         cudaFuncAttributeMaxDynamicSharedMemorySize, 61440);

    static cudaStream_t side = nullptr;
    static cudaEvent_t evFork = nullptr, evSide = nullptr;
    if (!side) {
        cudaStreamCreateWithFlags(&side, cudaStreamNonBlocking);
        cudaEventCreateWithFlags(&evFork, cudaEventDisableTiming);
        cudaEventCreateWithFlags(&evSide, cudaEventDisableTiming);
    }

    int blocks128 = (N + 127) / 128;
    int nb = (N + 255) / 256;
    int agg4_grid = (N + 3) / 4;
    int agg1_grid = (N + 7) / 8;
    int n4 = N * 64;

    // ---- fork side stream: CSR build + W2/W3 splits + stat zero ----
    cudaEventRecord(evFork, 0);
    cudaStreamWaitEvent(side, evFork, 0);
    zero_stats2_kernel<<<1, 256, 0, side>>>(sumsA, sumsqA, sumsB, sumsqB);
    zero_int_kernel<<<nb, 256, 0, side>>>(counts, N);
    count_kernel<<<(EE + 255) / 256, 256, 0, side>>>(ei, E, N, counts);
    scan_block_kernel<<<nb, 256, 0, side>>>(counts, start, bsums, N);
    scan_sums_kernel<<<1, 256, 0, side>>>(bsums, nb);
    add_offsets_kernel<<<nb, 256, 0, side>>>(start, bsums, woff, N, EE);
    fill_kernel<<<(EE + 255) / 256, 256, 0, side>>>(ei, E, N, woff, csr_src);
    split_hi_kernel<<<(256 * 256 / 4 + 255) / 256, 256, 0, side>>>(
        (const float4*)W2, (__half2*)w2h, 256 * 256 / 4);
    split_hilo_kernel<<<(64 * 256 / 4 + 255) / 256, 256, 0, side>>>(
        (const float4*)W3, (__half2*)w3h, (__half2*)w3l, 64 * 256 / 4);
    cudaEventRecord(evSide, side);

    // ---- layer 1: K=128, 1-term ----
    split_hi_kernel<<<(256 * 128 / 4 + 255) / 256, 256>>>(
        (const float4*)W1, (__half2*)w1h, 256 * 128 / 4);
    split_hi_kernel<<<(N * 128 / 4 + 255) / 256, 256>>>(
        (const float4*)x, (__half2*)ah, N * 128 / 4);
    gemm_mma<128, 1><<<dim3(blocks128, 2), 256, 40960>>>(ah, ah, w1h, w1h, h16, N, 128, 256,
                                                         a1s, a1d, als, ald);
    cudaStreamWaitEvent(0, evSide, 0);
    agg4_kernel<<<agg4_grid, 256>>>(start, csr_src, als, ald, h16, b1, acc, N, sumsA, sumsqA);
    bn_split_kernel<<<(n4 + 255) / 256, 256>>>((const float4*)acc, nullptr,
        (const float4*)gamma, (const float4*)beta, (const float4*)sumsA, (const float4*)sumsqA,
        1.0f / (float)N, n4, (float4*)res, (__half2*)ah, nullptr);

    // ---- layer 2: K=256, 1-term ----
    gemm_mma<128, 1><<<dim3(blocks128, 2), 256, 40960>>>(ah, ah, w2h, w2h, h16, N, 256, 256,
                                                         a2s, a2d, als, ald);
    agg4_kernel<<<agg4_grid, 256>>>(start, csr_src, als, ald, h16, b2, acc, N, sumsB, sumsqB);
    bn_split_kernel<<<(n4 + 255) / 256, 256>>>((const float4*)acc, (const float4*)res,
        (const float4*)gamma, (const float4*)beta, (const float4*)sumsB, (const float4*)sumsqB,
        1.0f / (float)N, n4, nullptr, (__half2*)ah, (__half2*)al);

    // ---- layer 3: K=256, 3-term ----
    gemm_mma<64, 3><<<dim3(blocks128, 1), 256, 61440>>>(ah, al, w3h, w3l, h16, N, 256, 64,
                                                        a3s, a3d, als, ald);
    agg1_kernel<<<agg1_grid, 256>>>(start, csr_src, als, ald, h16, b3, out, N);
}

// round 14
// speedup vs baseline: 1.0016x; 1.0016x over previous
#include <cuda_runtime.h>
#include <cuda_fp16.h>
#include <cstdint>

// ---------------- problem constants ----------------
#define HD   64
#define NHEADS 4
#define NMAX 50000
#define EMAX 400000
#define EEMAX (EMAX + NMAX)
#define FMAX 256

// ---------------- device scratch ----------------
__device__ __half g_h16[(size_t)NMAX * FMAX];  // gemm output (fp16, agg input)
__device__ float g_acc[(size_t)NMAX * FMAX];   // aggregation output
__device__ float g_res[(size_t)NMAX * FMAX];   // residual (bn1 out)
__device__ __half g_ah[(size_t)NMAX * FMAX];   // A hi (all layers)
__device__ __half g_al[(size_t)NMAX * FMAX];   // A lo (layer-3 input only)
__device__ __half g_w1h[FMAX * FMAX];
__device__ __half g_w2h[FMAX * FMAX];
__device__ __half g_w3h[HD * FMAX];
__device__ __half g_w3l[HD * FMAX];
__device__ float g_als[NMAX * NHEADS];
__device__ float g_ald[NMAX * NHEADS];
__device__ float g_sumsA[FMAX];
__device__ float g_sumsqA[FMAX];
__device__ float g_sumsB[FMAX];
__device__ float g_sumsqB[FMAX];
// CSR
__device__ int g_counts[NMAX + 1];
__device__ int g_start[NMAX + 1];
__device__ int g_woff[NMAX];
__device__ int g_bsums[256];
__device__ int g_csr_src[EEMAX];

// ---------------- PTX helpers ----------------
__device__ __forceinline__ uint32_t smem_u32(const void* p) {
    uint32_t a;
    asm("{ .reg .u64 t; cvta.to.shared.u64 t, %1; cvt.u32.u64 %0, t; }" : "=r"(a) : "l"(p));
    return a;
}
__device__ __forceinline__ void cp16z(uint32_t dst, const void* src, uint32_t nbytes) {
    asm volatile("cp.async.cg.shared.global [%0], [%1], 16, %2;"
                 :: "r"(dst), "l"(src), "r"(nbytes));
}
#define CP_COMMIT() asm volatile("cp.async.commit_group;" ::: "memory")
#define LDMATRIX_X4(R0, R1, R2, R3, ADDR)                                   \
    asm volatile("ldmatrix.sync.aligned.m8n8.x4.shared.b16 {%0,%1,%2,%3}, [%4];" \
                 : "=r"(R0), "=r"(R1), "=r"(R2), "=r"(R3) : "r"(ADDR))
#define MMA_FP16(C, A, B)                                                   \
    asm volatile("mma.sync.aligned.m16n8k16.row.col.f32.f16.f16.f32 "      \
                 "{%0,%1,%2,%3}, {%4,%5,%6,%7}, {%8,%9}, {%0,%1,%2,%3};"    \
                 : "+f"((C)[0]), "+f"((C)[1]), "+f"((C)[2]), "+f"((C)[3])   \
                 : "r"((A)[0]), "r"((A)[1]), "r"((A)[2]), "r"((A)[3]),      \
                   "r"((B)[0]), "r"((B)[1]))

__device__ __forceinline__ float expw(float v) {
    v = v > 0.f ? v : 0.2f * v;
    return __expf(v);
}

// ---------------- fp32 -> fp16 splits ----------------
__global__ void split_hilo_kernel(const float4* __restrict__ in,
                                  __half2* __restrict__ hi,
                                  __half2* __restrict__ lo, int n4) {
    int i = blockIdx.x * blockDim.x + threadIdx.x;
    if (i >= n4) return;
    float4 v = in[i];
    __half h0 = __float2half(v.x), h1 = __float2half(v.y);
    __half h2 = __float2half(v.z), h3 = __float2half(v.w);
    hi[i * 2 + 0] = __half2(h0, h1);
    hi[i * 2 + 1] = __half2(h2, h3);
    lo[i * 2 + 0] = __half2(__float2half(v.x - __half2float(h0)),
                            __float2half(v.y - __half2float(h1)));
    lo[i * 2 + 1] = __half2(__float2half(v.z - __half2float(h2)),
                            __float2half(v.w - __half2float(h3)));
}
__global__ void split_hi_kernel(const float4* __restrict__ in,
                                __half2* __restrict__ hi, int n4) {
    int i = blockIdx.x * blockDim.x + threadIdx.x;
    if (i >= n4) return;
    float4 v = in[i];
    hi[i * 2 + 0] = __half2(__float2half(v.x), __float2half(v.y));
    hi[i * 2 + 1] = __half2(__float2half(v.z), __float2half(v.w));
}

// ---------------- HMMA GEMM (fp16) + fused logits; fp16 C store ----------------
// NTILE=256: 512 threads, 4x4 warp grid, single A stage per CTA (TERMS=1 only).
// NTILE=64:  256 threads, 8x1 warp grid (TERMS=3).
template<int NTILE, int TERMS>
__global__ void __launch_bounds__((NTILE == 256) ? 512 : 256) gemm_mma(
    const __half* __restrict__ Ah, const __half* __restrict__ Al,
    const __half* __restrict__ Wh, const __half* __restrict__ Wl,
    __half* __restrict__ C16, int Nrows, int K, int NOUT,
    const float* __restrict__ a_s, const float* __restrict__ a_d,
    float* __restrict__ als, float* __restrict__ ald) {
    constexpr int TH = (NTILE == 256) ? 512 : 256;
    constexpr int RS = 40;
    constexpr int WN = (NTILE == 256) ? 4 : 1;   // warps along n (64 cols each)
    constexpr int WM = (TH / 32) / WN;           // warps along m
    constexpr int MT = 128 / (WM * 16);          // m16 tiles per warp (2 or 1)
    constexpr int HH = (NTILE == 256) ? 4 : 1;
    constexpr int NA = (TERMS == 3) ? 2 : 1;
    constexpr int NW = (TERMS >= 2) ? 2 : 1;
    constexpr int A_BYTES = 128 * RS * 2;
    constexpr int W_BYTES = NTILE * RS * 2;
    constexpr int STAGE = NA * A_BYTES + NW * W_BYTES;
    extern __shared__ char dsm[];
    const uint32_t sbase = smem_u32(dsm);
    const int tid = threadIdx.x, lane = tid & 31, wid = tid >> 5;
    const int wm = wid / WN, wn = wid % WN;
    const int row0 = blockIdx.x * 128, col0 = blockIdx.y * NTILE;

    const int a_row  = ((lane >> 3) & 1) * 8 + (lane & 7);
    const int a_koff = ((lane >> 4) & 1) * 8;
    const int b_row  = ((lane >> 4) & 1) * 8 + (lane & 7);
    const int b_koff = ((lane >> 3) & 1) * 8;
    const uint32_t a_off = (uint32_t)(((wm * 16 * MT + a_row) * RS + a_koff) * 2);
    const uint32_t b_off = (uint32_t)(((wn * 64 + b_row) * RS + b_koff) * 2);

    float acc[MT][8][4];
    #pragma unroll
    for (int mt = 0; mt < MT; mt++)
        #pragma unroll
        for (int nt = 0; nt < 8; nt++)
            #pragma unroll
            for (int j = 0; j < 4; j++) acc[mt][nt][j] = 0.f;

    const int nchunks = K >> 5;

    auto issue_chunk = [&](int ck) {
        const int st = ck & 1;
        const uint32_t ah_s = sbase + st * STAGE;
        const uint32_t al_s = ah_s + A_BYTES;
        const uint32_t wh_s = ah_s + NA * A_BYTES;
        const uint32_t wl_s = wh_s + W_BYTES;
        const int k0 = ck << 5;
        #pragma unroll
        for (int i = tid; i < 512; i += TH) {
            int r = i >> 2, c16 = i & 3;
            int gr = row0 + r;
            uint32_t nb = (gr < Nrows) ? 16u : 0u;
            if (gr >= Nrows) gr = Nrows - 1;
            uint32_t dof = (uint32_t)(r * RS + c16 * 8) * 2;
            cp16z(ah_s + dof, (const char*)(Ah + (size_t)gr * K + k0) + c16 * 16, nb);
            if (NA == 2)
                cp16z(al_s + dof, (const char*)(Al + (size_t)gr * K + k0) + c16 * 16, nb);
        }
        #pragma unroll
        for (int i = tid; i < NTILE * 4; i += TH) {
            int r = i >> 2, c16 = i & 3;
            uint32_t dof = (uint32_t)(r * RS + c16 * 8) * 2;
            cp16z(wh_s + dof, (const char*)(Wh + (size_t)(col0 + r) * K + k0) + c16 * 16, 16u);
            if (NW == 2)
                cp16z(wl_s + dof, (const char*)(Wl + (size_t)(col0 + r) * K + k0) + c16 * 16, 16u);
        }
        CP_COMMIT();
    };

    issue_chunk(0);
    for (int ck = 0; ck < nchunks; ck++) {
        if (ck + 1 < nchunks) {
            issue_chunk(ck + 1);
            asm volatile("cp.async.wait_group 1;" ::: "memory");
        } else {
            asm volatile("cp.async.wait_group 0;" ::: "memory");
        }
        __syncthreads();
        const int st = ck & 1;
        const uint32_t ahb = sbase + st * STAGE;
        const uint32_t alb = ahb + A_BYTES;
        const uint32_t whb = ahb + NA * A_BYTES;
        const uint32_t wlb = whb + W_BYTES;
        #pragma unroll
        for (int kk = 0; kk < 32; kk += 16) {
            uint32_t ah_f[MT][4], al_f[MT][4];
            #pragma unroll
            for (int mt = 0; mt < MT; mt++) {
                uint32_t o = a_off + (uint32_t)((mt * 16 * RS + kk) * 2);
                LDMATRIX_X4(ah_f[mt][0], ah_f[mt][1], ah_f[mt][2], ah_f[mt][3], ahb + o);
                if (NA == 2)
                    LDMATRIX_X4(al_f[mt][0], al_f[mt][1], al_f[mt][2], al_f[mt][3], alb + o);
            }
            uint32_t bh_f[8][2], bl_f[8][2];
            #pragma unroll
            for (int nt16 = 0; nt16 < 4; nt16++) {
                uint32_t o = b_off + (uint32_t)((nt16 * 16 * RS + kk) * 2);
                uint32_t r0, r1, r2, r3;
                LDMATRIX_X4(r0, r1, r2, r3, whb + o);
                bh_f[nt16 * 2 + 0][0] = r0; bh_f[nt16 * 2 + 0][1] = r1;
                bh_f[nt16 * 2 + 1][0] = r2; bh_f[nt16 * 2 + 1][1] = r3;
                if (NW == 2) {
                    LDMATRIX_X4(r0, r1, r2, r3, wlb + o);
                    bl_f[nt16 * 2 + 0][0] = r0; bl_f[nt16 * 2 + 0][1] = r1;
                    bl_f[nt16 * 2 + 1][0] = r2; bl_f[nt16 * 2 + 1][1] = r3;
                }
            }
            #pragma unroll
            for (int mt = 0; mt < MT; mt++)
                #pragma unroll
                for (int nt = 0; nt < 8; nt++) {
                    MMA_FP16(acc[mt][nt], ah_f[mt], bh_f[nt]);
                    if (TERMS >= 2)
                        MMA_FP16(acc[mt][nt], ah_f[mt], bl_f[nt]);
                    if (TERMS == 3)
                        MMA_FP16(acc[mt][nt], al_f[mt], bh_f[nt]);
                }
        }
        __syncthreads();
    }

    // ---- store C (fp16) ----
    #pragma unroll
    for (int mt = 0; mt < MT; mt++) {
        int mrow = row0 + wm * 16 * MT + mt * 16 + (lane >> 2);
        #pragma unroll
        for (int nt = 0; nt < 8; nt++) {
            int ncol = col0 + wn * 64 + nt * 8 + (lane & 3) * 2;
            __half2 p01 = __floats2half2_rn(acc[mt][nt][0], acc[mt][nt][1]);
            __half2 p23 = __floats2half2_rn(acc[mt][nt][2], acc[mt][nt][3]);
            if (mrow < Nrows)
                *(__half2*)&C16[(size_t)mrow * NOUT + ncol] = p01;
            if (mrow + 8 < Nrows)
                *(__half2*)&C16[(size_t)(mrow + 8) * NOUT + ncol] = p23;
        }
    }

    // ---- fused logits (from fp32 accumulators) ----
    const int hd = blockIdx.y * WN + wn;
    const float* avs = a_s + hd * HD;
    const float* avd = a_d + hd * HD;
    float as_v[16], ad_v[16];
    #pragma unroll
    for (int nt = 0; nt < 8; nt++) {
        int c = nt * 8 + (lane & 3) * 2;
        as_v[nt * 2 + 0] = avs[c];     as_v[nt * 2 + 1] = avs[c + 1];
        ad_v[nt * 2 + 0] = avd[c];     ad_v[nt * 2 + 1] = avd[c + 1];
    }
    #pragma unroll
    for (int mt = 0; mt < MT; mt++) {
        #pragma unroll
        for (int rr = 0; rr < 2; rr++) {
            float ds = 0.f, dd = 0.f;
            #pragma unroll
            for (int nt = 0; nt < 8; nt++) {
                float v0 = acc[mt][nt][rr * 2 + 0], v1 = acc[mt][nt][rr * 2 + 1];
                ds += v0 * as_v[nt * 2] + v1 * as_v[nt * 2 + 1];
                dd += v0 * ad_v[nt * 2] + v1 * ad_v[nt * 2 + 1];
            }
            ds += __shfl_xor_sync(0xffffffff, ds, 1);
            ds += __shfl_xor_sync(0xffffffff, ds, 2);
            dd += __shfl_xor_sync(0xffffffff, dd, 1);
            dd += __shfl_xor_sync(0xffffffff, dd, 2);
            int row = row0 + wm * 16 * MT + mt * 16 + rr * 8 + (lane >> 2);
            if ((lane & 3) == 0 && row < Nrows) {
                als[row * HH + hd] = ds;
                ald[row * HH + hd] = dd;
            }
        }
    }
}

// ---------------- CSR build ----------------
__global__ void zero_int_kernel(int* __restrict__ p, int n) {
    int i = blockIdx.x * blockDim.x + threadIdx.x;
    if (i < n) p[i] = 0;
}
__global__ void count_kernel(const int* __restrict__ ei, int E, int N, int* __restrict__ cnt) {
    int e = blockIdx.x * blockDim.x + threadIdx.x;
    int EE = E + N;
    if (e >= EE) return;
    int d = (e < E) ? ei[E + e] : e - E;
    atomicAdd(&cnt[d], 1);
}
__global__ void scan_block_kernel(const int* __restrict__ cnt, int* __restrict__ excl,
                                  int* __restrict__ bsums, int N) {
    __shared__ int sh[256];
    int tid = threadIdx.x;
    int i = blockIdx.x * 256 + tid;
    int v = (i < N) ? cnt[i] : 0;
    sh[tid] = v;
    __syncthreads();
    #pragma unroll
    for (int off = 1; off < 256; off <<= 1) {
        int t = (tid >= off) ? sh[tid - off] : 0;
        __syncthreads();
        sh[tid] += t;
        __syncthreads();
    }
    if (i < N) excl[i] = sh[tid] - v;
    if (tid == 255) bsums[blockIdx.x] = sh[255];
}
__global__ void scan_sums_kernel(int* __restrict__ bsums, int nb) {
    __shared__ int sh[256];
    int tid = threadIdx.x;
    int v = (tid < nb) ? bsums[tid] : 0;
    sh[tid] = v;
    __syncthreads();
    #pragma unroll
    for (int off = 1; off < 256; off <<= 1) {
        int t = (tid >= off) ? sh[tid - off] : 0;
        __syncthreads();
        sh[tid] += t;
        __syncthreads();
    }
    if (tid < nb) bsums[tid] = sh[tid] - v;
}
__global__ void add_offsets_kernel(int* __restrict__ excl, const int* __restrict__ bsums,
                                   int* __restrict__ woff, int N, int EE) {
    int i = blockIdx.x * 256 + threadIdx.x;
    if (i < N) {
        int v = excl[i] + bsums[blockIdx.x];
        excl[i] = v;
        woff[i] = v;
    }
    if (blockIdx.x == 0 && threadIdx.x == 0) excl[N] = EE;
}
__global__ void fill_kernel(const int* __restrict__ ei, int E, int N,
                            int* __restrict__ woff, int* __restrict__ csr_src) {
    int e = blockIdx.x * blockDim.x + threadIdx.x;
    int EE = E + N;
    if (e >= EE) return;
    int s, d;
    if (e < E) { s = ei[e]; d = ei[E + e]; }
    else       { s = d = e - E; }
    int pos = atomicAdd(&woff[d], 1);
    csr_src[pos] = s;
}

// ---------------- CSR aggregation, H=4 (fp16 h) ----------------
__global__ void __launch_bounds__(256) agg4_kernel(
    const int* __restrict__ start, const int* __restrict__ csr_src,
    const float* __restrict__ als, const float* __restrict__ ald,
    const __half* __restrict__ h16, const float* __restrict__ bias,
    float* __restrict__ out, int N,
    float* __restrict__ sums, float* __restrict__ sumsq) {
    __shared__ float s_s[256], s_q[256];
    int tid = threadIdx.x, lane = tid & 31, wid = tid >> 5;
    s_s[tid] = 0.f; s_q[tid] = 0.f;
    __syncthreads();
    int d = blockIdx.x * 4 + (wid >> 1);
    int half = wid & 1;
    if (d < N) {
        const float2* als2 = (const float2*)als;
        float2 aldv = ((const float2*)ald)[d * 2 + half];
        float den0 = 0.f, den1 = 0.f;
        float4 acc = make_float4(0.f, 0.f, 0.f, 0.f);
        const uint2* h4 = (const uint2*)h16;
        int c4 = half * 32 + lane;
        int j0 = start[d], j1 = start[d + 1];
        int j = j0;
        for (; j + 2 <= j1; j += 2) {
            int s0 = csr_src[j], s1 = csr_src[j + 1];
            float2 a0 = als2[s0 * 2 + half];
            float2 a1 = als2[s1 * 2 + half];
            uint2 u0 = h4[(size_t)s0 * 64 + c4];
            uint2 u1 = h4[(size_t)s1 * 64 + c4];
            float2 v0a = __half22float2(*(__half2*)&u0.x);
            float2 v0b = __half22float2(*(__half2*)&u0.y);
            float2 v1a = __half22float2(*(__half2*)&u1.x);
            float2 v1b = __half22float2(*(__half2*)&u1.y);
            float e00 = expw(a0.x + aldv.x), e01 = expw(a0.y + aldv.y);
            float e10 = expw(a1.x + aldv.x), e11 = expw(a1.y + aldv.y);
            den0 += e00 + e10;
            den1 += e01 + e11;
            float w0 = (lane < 16) ? e00 : e01;
            float w1 = (lane < 16) ? e10 : e11;
            acc.x += w0 * v0a.x + w1 * v1a.x;
            acc.y += w0 * v0a.y + w1 * v1a.y;
            acc.z += w0 * v0b.x + w1 * v1b.x;
            acc.w += w0 * v0b.y + w1 * v1b.y;
        }
        if (j < j1) {
            int s0 = csr_src[j];
            float2 a0 = als2[s0 * 2 + half];
            uint2 u0 = h4[(size_t)s0 * 64 + c4];
            float2 v0a = __half22float2(*(__half2*)&u0.x);
            float2 v0b = __half22float2(*(__half2*)&u0.y);
            float e00 = expw(a0.x + aldv.x), e01 = expw(a0.y + aldv.y);
            den0 += e00;
            den1 += e01;
            float w0 = (lane < 16) ? e00 : e01;
            acc.x += w0 * v0a.x; acc.y += w0 * v0a.y;
            acc.z += w0 * v0b.x; acc.w += w0 * v0b.y;
        }
        float inv = 1.f / ((lane < 16) ? den0 : den1);
        float4 bb = ((const float4*)bias)[c4];
        float4 r = make_float4(acc.x * inv + bb.x, acc.y * inv + bb.y,
                               acc.z * inv + bb.z, acc.w * inv + bb.w);
        ((float4*)(out + (size_t)d * 256))[c4] = r;
        int f = c4 * 4;
        atomicAdd(&s_s[f + 0], r.x); atomicAdd(&s_q[f + 0], r.x * r.x);
        atomicAdd(&s_s[f + 1], r.y); atomicAdd(&s_q[f + 1], r.y * r.y);
        atomicAdd(&s_s[f + 2], r.z); atomicAdd(&s_q[f + 2], r.z * r.z);
        atomicAdd(&s_s[f + 3], r.w); atomicAdd(&s_q[f + 3], r.w * r.w);
    }
    __syncthreads();
    atomicAdd(&sums[tid], s_s[tid]);
    atomicAdd(&sumsq[tid], s_q[tid]);
}

// ---------------- CSR aggregation, H=1 (F=64, fp16 h) ----------------
__global__ void __launch_bounds__(256) agg1_kernel(
    const int* __restrict__ start, const int* __restrict__ csr_src,
    const float* __restrict__ als, const float* __restrict__ ald,
    const __half* __restrict__ h16, const float* __restrict__ bias,
    float* __restrict__ out, int N) {
    int tid = threadIdx.x, lane = tid & 31, wid = tid >> 5;
    int d = blockIdx.x * 8 + wid;
    if (d >= N) return;
    float aldv = ald[d];
    float den = 0.f;
    float2 acc = make_float2(0.f, 0.f);
    const __half2* h2 = (const __half2*)h16;
    int j0 = start[d], j1 = start[d + 1];
    int j = j0;
    for (; j + 2 <= j1; j += 2) {
        int s0 = csr_src[j], s1 = csr_src[j + 1];
        float a0 = als[s0], a1 = als[s1];
        float2 v0 = __half22float2(h2[(size_t)s0 * 32 + lane]);
        float2 v1 = __half22float2(h2[(size_t)s1 * 32 + lane]);
        float e0 = expw(a0 + aldv), e1 = expw(a1 + aldv);
        den += e0 + e1;
        acc.x += e0 * v0.x + e1 * v1.x;
        acc.y += e0 * v0.y + e1 * v1.y;
    }
    if (j < j1) {
        int s0 = csr_src[j];
        float2 v0 = __half22float2(h2[(size_t)s0 * 32 + lane]);
        float e0 = expw(als[s0] + aldv);
        den += e0;
        acc.x += e0 * v0.x;
        acc.y += e0 * v0.y;
    }
    float inv = 1.f / den;
    float2 bb = ((const float2*)bias)[lane];
    ((float2*)(out + (size_t)d * 64))[lane] = make_float2(acc.x * inv + bb.x, acc.y * inv + bb.y);
}

__global__ void zero_stats2_kernel(float* __restrict__ sA, float* __restrict__ qA,
                                   float* __restrict__ sB, float* __restrict__ qB) {
    sA[threadIdx.x] = 0.f; qA[threadIdx.x] = 0.f;
    sB[threadIdx.x] = 0.f; qB[threadIdx.x] = 0.f;
}

// ---------------- BN + leakyReLU (+res) fused with fp16 split ----------------
__global__ void bn_split_kernel(const float4* __restrict__ x, const float4* __restrict__ res_in,
                                const float4* __restrict__ gamma4, const float4* __restrict__ beta4,
                                const float4* __restrict__ sums4, const float4* __restrict__ sumsq4,
                                float invn, int n4, float4* __restrict__ res_out,
                                __half2* __restrict__ hi, __half2* __restrict__ lo) {
    int i = blockIdx.x * blockDim.x + threadIdx.x;
    if (i >= n4) return;
    int f4 = i & 63;
    float4 xv = x[i], g = gamma4[f4], b = beta4[f4], s = sums4[f4], q = sumsq4[f4];
    float4 v;
    {
        float mu = s.x * invn, var = q.x * invn - mu * mu;
        v.x = g.x * (xv.x - mu) * rsqrtf(var + 1e-5f) + b.x;
        mu = s.y * invn; var = q.y * invn - mu * mu;
        v.y = g.y * (xv.y - mu) * rsqrtf(var + 1e-5f) + b.y;
        mu = s.z * invn; var = q.z * invn - mu * mu;
        v.z = g.z * (xv.z - mu) * rsqrtf(var + 1e-5f) + b.z;
        mu = s.w * invn; var = q.w * invn - mu * mu;
        v.w = g.w * (xv.w - mu) * rsqrtf(var + 1e-5f) + b.w;
    }
    v.x = v.x > 0.f ? v.x : 0.01f * v.x;
    v.y = v.y > 0.f ? v.y : 0.01f * v.y;
    v.z = v.z > 0.f ? v.z : 0.01f * v.z;
    v.w = v.w > 0.f ? v.w : 0.01f * v.w;
    if (res_in) {
        float4 r = res_in[i];
        v.x += r.x; v.y += r.y; v.z += r.z; v.w += r.w;
    }
    if (res_out) res_out[i] = v;
    __half h0 = __float2half(v.x), h1 = __float2half(v.y);
    __half h2 = __float2half(v.z), h3 = __float2half(v.w);
    hi[i * 2 + 0] = __half2(h0, h1);
    hi[i * 2 + 1] = __half2(h2, h3);
    if (lo) {
        lo[i * 2 + 0] = __half2(__float2half(v.x - __half2float(h0)),
                                __float2half(v.y - __half2float(h1)));
        lo[i * 2 + 1] = __half2(__float2half(v.z - __half2float(h2)),
                                __float2half(v.w - __half2float(h3)));
    }
}

// ---------------- host ----------------
extern "C" void kernel_launch(void* const* d_in, const int* in_sizes, int n_in,
                              void* d_out, int out_size) {
    const float* x     = (const float*)d_in[0];
    const int*   ei    = (const int*)d_in[1];
    const float* W1    = (const float*)d_in[2];
    const float* a1s   = (const float*)d_in[3];
    const float* a1d   = (const float*)d_in[4];
    const float* b1    = (const float*)d_in[5];
    const float* W2    = (const float*)d_in[6];
    const float* a2s   = (const float*)d_in[7];
    const float* a2d   = (const float*)d_in[8];
    const float* b2    = (const float*)d_in[9];
    const float* W3    = (const float*)d_in[10];
    const float* a3s   = (const float*)d_in[11];
    const float* a3d   = (const float*)d_in[12];
    const float* b3    = (const float*)d_in[13];
    const float* gamma = (const float*)d_in[14];
    const float* beta  = (const float*)d_in[15];
    float* out = (float*)d_out;

    int N = in_sizes[0] / (2 * HD);
    int E = in_sizes[1] / 2;
    int EE = E + N;

    float *acc, *res, *als, *ald, *sumsA, *sumsqA, *sumsB, *sumsqB;
    __half *h16, *ah, *al, *w1h, *w2h, *w3h, *w3l;
    int *counts, *start, *woff, *bsums, *csr_src;
    cudaGetSymbolAddress((void**)&h16,     g_h16);
    cudaGetSymbolAddress((void**)&acc,     g_acc);
    cudaGetSymbolAddress((void**)&res,     g_res);
    cudaGetSymbolAddress((void**)&ah,      g_ah);
    cudaGetSymbolAddress((void**)&al,      g_al);
    cudaGetSymbolAddress((void**)&w1h,     g_w1h);
    cudaGetSymbolAddress((void**)&w2h,     g_w2h);
    cudaGetSymbolAddress((void**)&w3h,     g_w3h);
    cudaGetSymbolAddress((void**)&w3l,     g_w3l);
    cudaGetSymbolAddress((void**)&als,     g_als);
    cudaGetSymbolAddress((void**)&ald,     g_ald);
    cudaGetSymbolAddress((void**)&sumsA,   g_sumsA);
    cudaGetSymbolAddress((void**)&sumsqA,  g_sumsqA);
    cudaGetSymbolAddress((void**)&sumsB,   g_sumsB);
    cudaGetSymbolAddress((void**)&sumsqB,  g_sumsqB);
    cudaGetSymbolAddress((void**)&counts,  g_counts);
    cudaGetSymbolAddress((void**)&start,   g_start);
    cudaGetSymbolAddress((void**)&woff,    g_woff);
    cudaGetSymbolAddress((void**)&bsums,   g_bsums);
    cudaGetSymbolAddress((void**)&csr_src, g_csr_src);

    cudaFuncSetAttribute((const void*)gemm_mma<256, 1>,
                         cudaFuncAttributeMaxDynamicSharedMemorySize, 61440);
    cudaFuncSetAttribute((const void*)gemm_mma<64, 3>,
                         cudaFuncAttributeMaxDynamicSharedMemorySize, 61440);

    static cudaStream_t side = nullptr;
    static cudaEvent_t evFork = nullptr, evSide = nullptr, evW1 = nullptr;
    if (!side) {
        cudaStreamCreateWithFlags(&side, cudaStreamNonBlocking);
        cudaEventCreateWithFlags(&evFork, cudaEventDisableTiming);
        cudaEventCreateWithFlags(&evSide, cudaEventDisableTiming);
        cudaEventCreateWithFlags(&evW1,   cudaEventDisableTiming);
    }

    int blocks128 = (N + 127) / 128;
    int nb = (N + 255) / 256;
    int agg4_grid = (N + 3) / 4;
    int agg1_grid = (N + 7) / 8;
    int n4 = N * 64;

    // ---- fork side stream: W1 split first (gemm1 waits on it), then CSR etc. ----
    cudaEventRecord(evFork, 0);
    cudaStreamWaitEvent(side, evFork, 0);
    split_hi_kernel<<<(256 * 128 / 4 + 255) / 256, 256, 0, side>>>(
        (const float4*)W1, (__half2*)w1h, 256 * 128 / 4);
    cudaEventRecord(evW1, side);
    zero_stats2_kernel<<<1, 256, 0, side>>>(sumsA, sumsqA, sumsB, sumsqB);
    zero_int_kernel<<<nb, 256, 0, side>>>(counts, N);
    count_kernel<<<(EE + 255) / 256, 256, 0, side>>>(ei, E, N, counts);
    scan_block_kernel<<<nb, 256, 0, side>>>(counts, start, bsums, N);
    scan_sums_kernel<<<1, 256, 0, side>>>(bsums, nb);
    add_offsets_kernel<<<nb, 256, 0, side>>>(start, bsums, woff, N, EE);
    fill_kernel<<<(EE + 255) / 256, 256, 0, side>>>(ei, E, N, woff, csr_src);
    split_hi_kernel<<<(256 * 256 / 4 + 255) / 256, 256, 0, side>>>(
        (const float4*)W2, (__half2*)w2h, 256 * 256 / 4);
    split_hilo_kernel<<<(64 * 256 / 4 + 255) / 256, 256, 0, side>>>(
        (const float4*)W3, (__half2*)w3h, (__half2*)w3l, 64 * 256 / 4);
    cudaEventRecord(evSide, side);

    // ---- layer 1: K=128, 1-term, 128x256 tile ----
    split_hi_kernel<<<(N * 128 / 4 + 255) / 256, 256>>>(
        (const float4*)x, (__half2*)ah, N * 128 / 4);
    cudaStreamWaitEvent(0, evW1, 0);
    gemm_mma<256, 1><<<blocks128, 512, 61440>>>(ah, ah, w1h, w1h, h16, N, 128, 256,
                                                a1s, a1d, als, ald);
    cudaStreamWaitEvent(0, evSide, 0);
    agg4_kernel<<<agg4_grid, 256>>>(start, csr_src, als, ald, h16, b1, acc, N, sumsA, sumsqA);
    bn_split_kernel<<<(n4 + 255) / 256, 256>>>((const float4*)acc, nullptr,
        (const float4*)gamma, (const float4*)beta, (const float4*)sumsA, (const float4*)sumsqA,
        1.0f / (float)N, n4, (float4*)res, (__half2*)ah, nullptr);

    // ---- layer 2: K=256, 1-term, 128x256 tile ----
    gemm_mma<256, 1><<<blocks128, 512, 61440>>>(ah, ah, w2h, w2h, h16, N, 256, 256,
                                                a2s, a2d, als, ald);
    agg4_kernel<<<agg4_grid, 256>>>(start, csr_src, als, ald, h16, b2, acc, N, sumsB, sumsqB);
    bn_split_kernel<<<(n4 + 255) / 256, 256>>>((const float4*)acc, (const float4*)res,
        (const float4*)gamma, (const float4*)beta, (const float4*)sumsB, (const float4*)sumsqB,
        1.0f / (float)N, n4, nullptr, (__half2*)ah, (__half2*)al);

    // ---- layer 3: K=256, 3-term ----
    gemm_mma<64, 3><<<blocks128, 256, 61440>>>(ah, al, w3h, w3l, h16, N, 256, 64,
                                               a3s, a3d, als, ald);
    agg1_kernel<<<agg1_grid, 256>>>(start, csr_src, als, ald, h16, b3, out, N);
}

// round 15
// speedup vs baseline: 1.3747x; 1.3725x over previous
#include <cuda_runtime.h>
#include <cuda_fp16.h>
#include <cstdint>

// ---------------- problem constants ----------------
#define HD   64
#define NHEADS 4
#define NMAX 50000
#define EMAX 400000
#define EEMAX (EMAX + NMAX)
#define FMAX 256

// ---------------- device scratch ----------------
__device__ __half g_h16[(size_t)NMAX * FMAX];  // gemm output (fp16, agg input)
__device__ float g_acc[(size_t)NMAX * FMAX];   // aggregation output
__device__ float g_res[(size_t)NMAX * FMAX];   // residual (bn1 out)
__device__ __half g_ah[(size_t)NMAX * FMAX];   // A hi (all layers)
__device__ __half g_al[(size_t)NMAX * FMAX];   // A lo (layer-3 input only)
__device__ __half g_w1h[FMAX * FMAX];
__device__ __half g_w2h[FMAX * FMAX];
__device__ __half g_w3h[HD * FMAX];
__device__ __half g_w3l[HD * FMAX];
__device__ float g_als[NMAX * NHEADS];
__device__ float g_ald[NMAX * NHEADS];
__device__ float g_sumsA[FMAX];
__device__ float g_sumsqA[FMAX];
__device__ float g_sumsB[FMAX];
__device__ float g_sumsqB[FMAX];
// CSR
__device__ int g_counts[NMAX + 1];
__device__ int g_start[NMAX + 1];
__device__ int g_woff[NMAX];
__device__ int g_bsums[256];
__device__ int g_csr_src[EEMAX];

// ---------------- PTX helpers ----------------
__device__ __forceinline__ uint32_t smem_u32(const void* p) {
    uint32_t a;
    asm("{ .reg .u64 t; cvta.to.shared.u64 t, %1; cvt.u32.u64 %0, t; }" : "=r"(a) : "l"(p));
    return a;
}
__device__ __forceinline__ void cp16z(uint32_t dst, const void* src, uint32_t nbytes) {
    asm volatile("cp.async.cg.shared.global [%0], [%1], 16, %2;"
                 :: "r"(dst), "l"(src), "r"(nbytes));
}
#define CP_COMMIT() asm volatile("cp.async.commit_group;" ::: "memory")
#define LDMATRIX_X4(R0, R1, R2, R3, ADDR)                                   \
    asm volatile("ldmatrix.sync.aligned.m8n8.x4.shared.b16 {%0,%1,%2,%3}, [%4];" \
                 : "=r"(R0), "=r"(R1), "=r"(R2), "=r"(R3) : "r"(ADDR))
#define MMA_FP16(C, A, B)                                                   \
    asm volatile("mma.sync.aligned.m16n8k16.row.col.f32.f16.f16.f32 "      \
                 "{%0,%1,%2,%3}, {%4,%5,%6,%7}, {%8,%9}, {%0,%1,%2,%3};"    \
                 : "+f"((C)[0]), "+f"((C)[1]), "+f"((C)[2]), "+f"((C)[3])   \
                 : "r"((A)[0]), "r"((A)[1]), "r"((A)[2]), "r"((A)[3]),      \
                   "r"((B)[0]), "r"((B)[1]))

__device__ __forceinline__ float expw(float v) {
    v = v > 0.f ? v : 0.2f * v;
    return __expf(v);
}

// ---------------- fp32 -> fp16 splits ----------------
__global__ void split_hilo_kernel(const float4* __restrict__ in,
                                  __half2* __restrict__ hi,
                                  __half2* __restrict__ lo, int n4) {
    int i = blockIdx.x * blockDim.x + threadIdx.x;
    if (i >= n4) return;
    float4 v = in[i];
    __half h0 = __float2half(v.x), h1 = __float2half(v.y);
    __half h2 = __float2half(v.z), h3 = __float2half(v.w);
    hi[i * 2 + 0] = __half2(h0, h1);
    hi[i * 2 + 1] = __half2(h2, h3);
    lo[i * 2 + 0] = __half2(__float2half(v.x - __half2float(h0)),
                            __float2half(v.y - __half2float(h1)));
    lo[i * 2 + 1] = __half2(__float2half(v.z - __half2float(h2)),
                            __float2half(v.w - __half2float(h3)));
}
__global__ void split_hi_kernel(const float4* __restrict__ in,
                                __half2* __restrict__ hi, int n4) {
    int i = blockIdx.x * blockDim.x + threadIdx.x;
    if (i >= n4) return;
    float4 v = in[i];
    hi[i * 2 + 0] = __half2(__float2half(v.x), __float2half(v.y));
    hi[i * 2 + 1] = __half2(__float2half(v.z), __float2half(v.w));
}

// ---------------- HMMA GEMM (fp16) + fused logits; fp16 C store ----------------
template<int NTILE, int TERMS>
__global__ void __launch_bounds__((NTILE == 256) ? 512 : 256) gemm_mma(
    const __half* __restrict__ Ah, const __half* __restrict__ Al,
    const __half* __restrict__ Wh, const __half* __restrict__ Wl,
    __half* __restrict__ C16, int Nrows, int K, int NOUT,
    const float* __restrict__ a_s, const float* __restrict__ a_d,
    float* __restrict__ als, float* __restrict__ ald) {
    constexpr int TH = (NTILE == 256) ? 512 : 256;
    constexpr int RS = 40;
    constexpr int WN = (NTILE == 256) ? 4 : 1;
    constexpr int WM = (TH / 32) / WN;
    constexpr int MT = 128 / (WM * 16);
    constexpr int HH = (NTILE == 256) ? 4 : 1;
    constexpr int NA = (TERMS == 3) ? 2 : 1;
    constexpr int NW = (TERMS >= 2) ? 2 : 1;
    constexpr int A_BYTES = 128 * RS * 2;
    constexpr int W_BYTES = NTILE * RS * 2;
    constexpr int STAGE = NA * A_BYTES + NW * W_BYTES;
    extern __shared__ char dsm[];
    const uint32_t sbase = smem_u32(dsm);
    const int tid = threadIdx.x, lane = tid & 31, wid = tid >> 5;
    const int wm = wid / WN, wn = wid % WN;
    const int row0 = blockIdx.x * 128, col0 = blockIdx.y * NTILE;

    const int a_row  = ((lane >> 3) & 1) * 8 + (lane & 7);
    const int a_koff = ((lane >> 4) & 1) * 8;
    const int b_row  = ((lane >> 4) & 1) * 8 + (lane & 7);
    const int b_koff = ((lane >> 3) & 1) * 8;
    const uint32_t a_off = (uint32_t)(((wm * 16 * MT + a_row) * RS + a_koff) * 2);
    const uint32_t b_off = (uint32_t)(((wn * 64 + b_row) * RS + b_koff) * 2);

    float acc[MT][8][4];
    #pragma unroll
    for (int mt = 0; mt < MT; mt++)
        #pragma unroll
        for (int nt = 0; nt < 8; nt++)
            #pragma unroll
            for (int j = 0; j < 4; j++) acc[mt][nt][j] = 0.f;

    const int nchunks = K >> 5;

    auto issue_chunk = [&](int ck) {
        const int st = ck & 1;
        const uint32_t ah_s = sbase + st * STAGE;
        const uint32_t al_s = ah_s + A_BYTES;
        const uint32_t wh_s = ah_s + NA * A_BYTES;
        const uint32_t wl_s = wh_s + W_BYTES;
        const int k0 = ck << 5;
        #pragma unroll
        for (int i = tid; i < 512; i += TH) {
            int r = i >> 2, c16 = i & 3;
            int gr = row0 + r;
            uint32_t nb = (gr < Nrows) ? 16u : 0u;
            if (gr >= Nrows) gr = Nrows - 1;
            uint32_t dof = (uint32_t)(r * RS + c16 * 8) * 2;
            cp16z(ah_s + dof, (const char*)(Ah + (size_t)gr * K + k0) + c16 * 16, nb);
            if (NA == 2)
                cp16z(al_s + dof, (const char*)(Al + (size_t)gr * K + k0) + c16 * 16, nb);
        }
        #pragma unroll
        for (int i = tid; i < NTILE * 4; i += TH) {
            int r = i >> 2, c16 = i & 3;
            uint32_t dof = (uint32_t)(r * RS + c16 * 8) * 2;
            cp16z(wh_s + dof, (const char*)(Wh + (size_t)(col0 + r) * K + k0) + c16 * 16, 16u);
            if (NW == 2)
                cp16z(wl_s + dof, (const char*)(Wl + (size_t)(col0 + r) * K + k0) + c16 * 16, 16u);
        }
        CP_COMMIT();
    };

    issue_chunk(0);
    for (int ck = 0; ck < nchunks; ck++) {
        if (ck + 1 < nchunks) {
            issue_chunk(ck + 1);
            asm volatile("cp.async.wait_group 1;" ::: "memory");
        } else {
            asm volatile("cp.async.wait_group 0;" ::: "memory");
        }
        __syncthreads();
        const int st = ck & 1;
        const uint32_t ahb = sbase + st * STAGE;
        const uint32_t alb = ahb + A_BYTES;
        const uint32_t whb = ahb + NA * A_BYTES;
        const uint32_t wlb = whb + W_BYTES;
        #pragma unroll
        for (int kk = 0; kk < 32; kk += 16) {
            uint32_t ah_f[MT][4], al_f[MT][4];
            #pragma unroll
            for (int mt = 0; mt < MT; mt++) {
                uint32_t o = a_off + (uint32_t)((mt * 16 * RS + kk) * 2);
                LDMATRIX_X4(ah_f[mt][0], ah_f[mt][1], ah_f[mt][2], ah_f[mt][3], ahb + o);
                if (NA == 2)
                    LDMATRIX_X4(al_f[mt][0], al_f[mt][1], al_f[mt][2], al_f[mt][3], alb + o);
            }
            uint32_t bh_f[8][2], bl_f[8][2];
            #pragma unroll
            for (int nt16 = 0; nt16 < 4; nt16++) {
                uint32_t o = b_off + (uint32_t)((nt16 * 16 * RS + kk) * 2);
                uint32_t r0, r1, r2, r3;
                LDMATRIX_X4(r0, r1, r2, r3, whb + o);
                bh_f[nt16 * 2 + 0][0] = r0; bh_f[nt16 * 2 + 0][1] = r1;
                bh_f[nt16 * 2 + 1][0] = r2; bh_f[nt16 * 2 + 1][1] = r3;
                if (NW == 2) {
                    LDMATRIX_X4(r0, r1, r2, r3, wlb + o);
                    bl_f[nt16 * 2 + 0][0] = r0; bl_f[nt16 * 2 + 0][1] = r1;
                    bl_f[nt16 * 2 + 1][0] = r2; bl_f[nt16 * 2 + 1][1] = r3;
                }
            }
            #pragma unroll
            for (int mt = 0; mt < MT; mt++)
                #pragma unroll
                for (int nt = 0; nt < 8; nt++) {
                    MMA_FP16(acc[mt][nt], ah_f[mt], bh_f[nt]);
                    if (TERMS >= 2)
                        MMA_FP16(acc[mt][nt], ah_f[mt], bl_f[nt]);
                    if (TERMS == 3)
                        MMA_FP16(acc[mt][nt], al_f[mt], bh_f[nt]);
                }
        }
        __syncthreads();
    }

    // ---- store C (fp16) ----
    #pragma unroll
    for (int mt = 0; mt < MT; mt++) {
        int mrow = row0 + wm * 16 * MT + mt * 16 + (lane >> 2);
        #pragma unroll
        for (int nt = 0; nt < 8; nt++) {
            int ncol = col0 + wn * 64 + nt * 8 + (lane & 3) * 2;
            __half2 p01 = __floats2half2_rn(acc[mt][nt][0], acc[mt][nt][1]);
            __half2 p23 = __floats2half2_rn(acc[mt][nt][2], acc[mt][nt][3]);
            if (mrow < Nrows)
                *(__half2*)&C16[(size_t)mrow * NOUT + ncol] = p01;
            if (mrow + 8 < Nrows)
                *(__half2*)&C16[(size_t)(mrow + 8) * NOUT + ncol] = p23;
        }
    }

    // ---- fused logits ----
    const int hd = blockIdx.y * WN + wn;
    const float* avs = a_s + hd * HD;
    const float* avd = a_d + hd * HD;
    float as_v[16], ad_v[16];
    #pragma unroll
    for (int nt = 0; nt < 8; nt++) {
        int c = nt * 8 + (lane & 3) * 2;
        as_v[nt * 2 + 0] = avs[c];     as_v[nt * 2 + 1] = avs[c + 1];
        ad_v[nt * 2 + 0] = avd[c];     ad_v[nt * 2 + 1] = avd[c + 1];
    }
    #pragma unroll
    for (int mt = 0; mt < MT; mt++) {
        #pragma unroll
        for (int rr = 0; rr < 2; rr++) {
            float ds = 0.f, dd = 0.f;
            #pragma unroll
            for (int nt = 0; nt < 8; nt++) {
                float v0 = acc[mt][nt][rr * 2 + 0], v1 = acc[mt][nt][rr * 2 + 1];
                ds += v0 * as_v[nt * 2] + v1 * as_v[nt * 2 + 1];
                dd += v0 * ad_v[nt * 2] + v1 * ad_v[nt * 2 + 1];
            }
            ds += __shfl_xor_sync(0xffffffff, ds, 1);
            ds += __shfl_xor_sync(0xffffffff, ds, 2);
            dd += __shfl_xor_sync(0xffffffff, dd, 1);
            dd += __shfl_xor_sync(0xffffffff, dd, 2);
            int row = row0 + wm * 16 * MT + mt * 16 + rr * 8 + (lane >> 2);
            if ((lane & 3) == 0 && row < Nrows) {
                als[row * HH + hd] = ds;
                ald[row * HH + hd] = dd;
            }
        }
    }
}

// ---------------- CSR build ----------------
__global__ void zero_int_kernel(int* __restrict__ p, int n) {
    int i = blockIdx.x * blockDim.x + threadIdx.x;
    if (i < n) p[i] = 0;
}
__global__ void count_kernel(const int* __restrict__ ei, int E, int N, int* __restrict__ cnt) {
    int e = blockIdx.x * blockDim.x + threadIdx.x;
    int EE = E + N;
    if (e >= EE) return;
    int d = (e < E) ? ei[E + e] : e - E;
    atomicAdd(&cnt[d], 1);
}
__global__ void scan_block_kernel(const int* __restrict__ cnt, int* __restrict__ excl,
                                  int* __restrict__ bsums, int N) {
    __shared__ int sh[256];
    int tid = threadIdx.x;
    int i = blockIdx.x * 256 + tid;
    int v = (i < N) ? cnt[i] : 0;
    sh[tid] = v;
    __syncthreads();
    #pragma unroll
    for (int off = 1; off < 256; off <<= 1) {
        int t = (tid >= off) ? sh[tid - off] : 0;
        __syncthreads();
        sh[tid] += t;
        __syncthreads();
    }
    if (i < N) excl[i] = sh[tid] - v;
    if (tid == 255) bsums[blockIdx.x] = sh[255];
}
__global__ void scan_sums_kernel(int* __restrict__ bsums, int nb) {
    __shared__ int sh[256];
    int tid = threadIdx.x;
    int v = (tid < nb) ? bsums[tid] : 0;
    sh[tid] = v;
    __syncthreads();
    #pragma unroll
    for (int off = 1; off < 256; off <<= 1) {
        int t = (tid >= off) ? sh[tid - off] : 0;
        __syncthreads();
        sh[tid] += t;
        __syncthreads();
    }
    if (tid < nb) bsums[tid] = sh[tid] - v;
}
__global__ void add_offsets_kernel(int* __restrict__ excl, const int* __restrict__ bsums,
                                   int* __restrict__ woff, int N, int EE) {
    int i = blockIdx.x * 256 + threadIdx.x;
    if (i < N) {
        int v = excl[i] + bsums[blockIdx.x];
        excl[i] = v;
        woff[i] = v;
    }
    if (blockIdx.x == 0 && threadIdx.x == 0) excl[N] = EE;
}
__global__ void fill_kernel(const int* __restrict__ ei, int E, int N,
                            int* __restrict__ woff, int* __restrict__ csr_src) {
    int e = blockIdx.x * blockDim.x + threadIdx.x;
    int EE = E + N;
    if (e >= EE) return;
    int s, d;
    if (e < E) { s = ei[e]; d = ei[E + e]; }
    else       { s = d = e - E; }
    int pos = atomicAdd(&woff[d], 1);
    csr_src[pos] = s;
}

// ---------------- CSR aggregation, H=4 (fp16 h, 16 nodes/block) ----------------
__global__ void __launch_bounds__(256) agg4_kernel(
    const int* __restrict__ start, const int* __restrict__ csr_src,
    const float* __restrict__ als, const float* __restrict__ ald,
    const __half* __restrict__ h16, const float* __restrict__ bias,
    float* __restrict__ out, int N,
    float* __restrict__ sums, float* __restrict__ sumsq) {
    __shared__ float s_s[256], s_q[256];
    int tid = threadIdx.x, lane = tid & 31, wid = tid >> 5;
    s_s[tid] = 0.f; s_q[tid] = 0.f;
    __syncthreads();
    int half = wid & 1;
    int c4 = half * 32 + lane;
    float4 bb = ((const float4*)bias)[c4];
    float ls0 = 0.f, ls1 = 0.f, ls2 = 0.f, ls3 = 0.f;
    float lq0 = 0.f, lq1 = 0.f, lq2 = 0.f, lq3 = 0.f;
    const float2* als2 = (const float2*)als;
    const uint2* h4 = (const uint2*)h16;

    #pragma unroll
    for (int it = 0; it < 4; it++) {
        int d = blockIdx.x * 16 + it * 4 + (wid >> 1);
        if (d >= N) continue;
        float2 aldv = ((const float2*)ald)[d * 2 + half];
        float den0 = 0.f, den1 = 0.f;
        float4 acc = make_float4(0.f, 0.f, 0.f, 0.f);
        int j0 = start[d], j1 = start[d + 1];
        int j = j0;
        for (; j + 2 <= j1; j += 2) {
            int s0 = csr_src[j], s1 = csr_src[j + 1];
            float2 a0 = als2[s0 * 2 + half];
            float2 a1 = als2[s1 * 2 + half];
            uint2 u0 = h4[(size_t)s0 * 64 + c4];
            uint2 u1 = h4[(size_t)s1 * 64 + c4];
            float2 v0a = __half22float2(*(__half2*)&u0.x);
            float2 v0b = __half22float2(*(__half2*)&u0.y);
            float2 v1a = __half22float2(*(__half2*)&u1.x);
            float2 v1b = __half22float2(*(__half2*)&u1.y);
            float e00 = expw(a0.x + aldv.x), e01 = expw(a0.y + aldv.y);
            float e10 = expw(a1.x + aldv.x), e11 = expw(a1.y + aldv.y);
            den0 += e00 + e10;
            den1 += e01 + e11;
            float w0 = (lane < 16) ? e00 : e01;
            float w1 = (lane < 16) ? e10 : e11;
            acc.x += w0 * v0a.x + w1 * v1a.x;
            acc.y += w0 * v0a.y + w1 * v1a.y;
            acc.z += w0 * v0b.x + w1 * v1b.x;
            acc.w += w0 * v0b.y + w1 * v1b.y;
        }
        if (j < j1) {
            int s0 = csr_src[j];
            float2 a0 = als2[s0 * 2 + half];
            uint2 u0 = h4[(size_t)s0 * 64 + c4];
            float2 v0a = __half22float2(*(__half2*)&u0.x);
            float2 v0b = __half22float2(*(__half2*)&u0.y);
            float e00 = expw(a0.x + aldv.x), e01 = expw(a0.y + aldv.y);
            den0 += e00;
            den1 += e01;
            float w0 = (lane < 16) ? e00 : e01;
            acc.x += w0 * v0a.x; acc.y += w0 * v0a.y;
            acc.z += w0 * v0b.x; acc.w += w0 * v0b.y;
        }
        float inv = 1.f / ((lane < 16) ? den0 : den1);
        float4 r = make_float4(acc.x * inv + bb.x, acc.y * inv + bb.y,
                               acc.z * inv + bb.z, acc.w * inv + bb.w);
        ((float4*)(out + (size_t)d * 256))[c4] = r;
        ls0 += r.x; lq0 += r.x * r.x;
        ls1 += r.y; lq1 += r.y * r.y;
        ls2 += r.z; lq2 += r.z * r.z;
        ls3 += r.w; lq3 += r.w * r.w;
    }
    int f = c4 * 4;
    atomicAdd(&s_s[f + 0], ls0); atomicAdd(&s_q[f + 0], lq0);
    atomicAdd(&s_s[f + 1], ls1); atomicAdd(&s_q[f + 1], lq1);
    atomicAdd(&s_s[f + 2], ls2); atomicAdd(&s_q[f + 2], lq2);
    atomicAdd(&s_s[f + 3], ls3); atomicAdd(&s_q[f + 3], lq3);
    __syncthreads();
    atomicAdd(&sums[tid], s_s[tid]);
    atomicAdd(&sumsq[tid], s_q[tid]);
}

// ---------------- CSR aggregation, H=1 (F=64, fp16 h) ----------------
__global__ void __launch_bounds__(256) agg1_kernel(
    const int* __restrict__ start, const int* __restrict__ csr_src,
    const float* __restrict__ als, const float* __restrict__ ald,
    const __half* __restrict__ h16, const float* __restrict__ bias,
    float* __restrict__ out, int N) {
    int tid = threadIdx.x, lane = tid & 31, wid = tid >> 5;
    int d = blockIdx.x * 8 + wid;
    if (d >= N) return;
    float aldv = ald[d];
    float den = 0.f;
    float2 acc = make_float2(0.f, 0.f);
    const __half2* h2 = (const __half2*)h16;
    int j0 = start[d], j1 = start[d + 1];
    int j = j0;
    for (; j + 2 <= j1; j += 2) {
        int s0 = csr_src[j], s1 = csr_src[j + 1];
        float a0 = als[s0], a1 = als[s1];
        float2 v0 = __half22float2(h2[(size_t)s0 * 32 + lane]);
        float2 v1 = __half22float2(h2[(size_t)s1 * 32 + lane]);
        float e0 = expw(a0 + aldv), e1 = expw(a1 + aldv);
        den += e0 + e1;
        acc.x += e0 * v0.x + e1 * v1.x;
        acc.y += e0 * v0.y + e1 * v1.y;
    }
    if (j < j1) {
        int s0 = csr_src[j];
        float2 v0 = __half22float2(h2[(size_t)s0 * 32 + lane]);
        float e0 = expw(als[s0] + aldv);
        den += e0;
        acc.x += e0 * v0.x;
        acc.y += e0 * v0.y;
    }
    float inv = 1.f / den;
    float2 bb = ((const float2*)bias)[lane];
    ((float2*)(out + (size_t)d * 64))[lane] = make_float2(acc.x * inv + bb.x, acc.y * inv + bb.y);
}

__global__ void zero_stats2_kernel(float* __restrict__ sA, float* __restrict__ qA,
                                   float* __restrict__ sB, float* __restrict__ qB) {
    sA[threadIdx.x] = 0.f; qA[threadIdx.x] = 0.f;
    sB[threadIdx.x] = 0.f; qB[threadIdx.x] = 0.f;
}

// ---------------- BN + leakyReLU (+res) fused with fp16 split ----------------
__global__ void bn_split_kernel(const float4* __restrict__ x, const float4* __restrict__ res_in,
                                const float4* __restrict__ gamma4, const float4* __restrict__ beta4,
                                const float4* __restrict__ sums4, const float4* __restrict__ sumsq4,
                                float invn, int n4, float4* __restrict__ res_out,
                                __half2* __restrict__ hi, __half2* __restrict__ lo) {
    int i = blockIdx.x * blockDim.x + threadIdx.x;
    if (i >= n4) return;
    int f4 = i & 63;
    float4 xv = x[i], g = gamma4[f4], b = beta4[f4], s = sums4[f4], q = sumsq4[f4];
    float4 v;
    {
        float mu = s.x * invn, var = q.x * invn - mu * mu;
        v.x = g.x * (xv.x - mu) * rsqrtf(var + 1e-5f) + b.x;
        mu = s.y * invn; var = q.y * invn - mu * mu;
        v.y = g.y * (xv.y - mu) * rsqrtf(var + 1e-5f) + b.y;
        mu = s.z * invn; var = q.z * invn - mu * mu;
        v.z = g.z * (xv.z - mu) * rsqrtf(var + 1e-5f) + b.z;
        mu = s.w * invn; var = q.w * invn - mu * mu;
        v.w = g.w * (xv.w - mu) * rsqrtf(var + 1e-5f) + b.w;
    }
    v.x = v.x > 0.f ? v.x : 0.01f * v.x;
    v.y = v.y > 0.f ? v.y : 0.01f * v.y;
    v.z = v.z > 0.f ? v.z : 0.01f * v.z;
    v.w = v.w > 0.f ? v.w : 0.01f * v.w;
    if (res_in) {
        float4 r = res_in[i];
        v.x += r.x; v.y += r.y; v.z += r.z; v.w += r.w;
    }
    if (res_out) res_out[i] = v;
    __half h0 = __float2half(v.x), h1 = __float2half(v.y);
    __half h2 = __float2half(v.z), h3 = __float2half(v.w);
    hi[i * 2 + 0] = __half2(h0, h1);
    hi[i * 2 + 1] = __half2(h2, h3);
    if (lo) {
        lo[i * 2 + 0] = __half2(__float2half(v.x - __half2float(h0)),
                                __float2half(v.y - __half2float(h1)));
        lo[i * 2 + 1] = __half2(__float2half(v.z - __half2float(h2)),
                                __float2half(v.w - __half2float(h3)));
    }
}

// ---------------- host ----------------
extern "C" void kernel_launch(void* const* d_in, const int* in_sizes, int n_in,
                              void* d_out, int out_size) {
    const float* x     = (const float*)d_in[0];
    const int*   ei    = (const int*)d_in[1];
    const float* W1    = (const float*)d_in[2];
    const float* a1s   = (const float*)d_in[3];
    const float* a1d   = (const float*)d_in[4];
    const float* b1    = (const float*)d_in[5];
    const float* W2    = (const float*)d_in[6];
    const float* a2s   = (const float*)d_in[7];
    const float* a2d   = (const float*)d_in[8];
    const float* b2    = (const float*)d_in[9];
    const float* W3    = (const float*)d_in[10];
    const float* a3s   = (const float*)d_in[11];
    const float* a3d   = (const float*)d_in[12];
    const float* b3    = (const float*)d_in[13];
    const float* gamma = (const float*)d_in[14];
    const float* beta  = (const float*)d_in[15];
    float* out = (float*)d_out;

    int N = in_sizes[0] / (2 * HD);
    int E = in_sizes[1] / 2;
    int EE = E + N;

    float *acc, *res, *als, *ald, *sumsA, *sumsqA, *sumsB, *sumsqB;
    __half *h16, *ah, *al, *w1h, *w2h, *w3h, *w3l;
    int *counts, *start, *woff, *bsums, *csr_src;
    cudaGetSymbolAddress((void**)&h16,     g_h16);
    cudaGetSymbolAddress((void**)&acc,     g_acc);
    cudaGetSymbolAddress((void**)&res,     g_res);
    cudaGetSymbolAddress((void**)&ah,      g_ah);
    cudaGetSymbolAddress((void**)&al,      g_al);
    cudaGetSymbolAddress((void**)&w1h,     g_w1h);
    cudaGetSymbolAddress((void**)&w2h,     g_w2h);
    cudaGetSymbolAddress((void**)&w3h,     g_w3h);
    cudaGetSymbolAddress((void**)&w3l,     g_w3l);
    cudaGetSymbolAddress((void**)&als,     g_als);
    cudaGetSymbolAddress((void**)&ald,     g_ald);
    cudaGetSymbolAddress((void**)&sumsA,   g_sumsA);
    cudaGetSymbolAddress((void**)&sumsqA,  g_sumsqA);
    cudaGetSymbolAddress((void**)&sumsB,   g_sumsB);
    cudaGetSymbolAddress((void**)&sumsqB,  g_sumsqB);
    cudaGetSymbolAddress((void**)&counts,  g_counts);
    cudaGetSymbolAddress((void**)&start,   g_start);
    cudaGetSymbolAddress((void**)&woff,    g_woff);
    cudaGetSymbolAddress((void**)&bsums,   g_bsums);
    cudaGetSymbolAddress((void**)&csr_src, g_csr_src);

    cudaFuncSetAttribute((const void*)gemm_mma<256, 1>,
                         cudaFuncAttributeMaxDynamicSharedMemorySize, 61440);
    cudaFuncSetAttribute((const void*)gemm_mma<64, 3>,
                         cudaFuncAttributeMaxDynamicSharedMemorySize, 61440);

    static cudaStream_t side = nullptr;
    static cudaEvent_t evFork = nullptr, evSide = nullptr, evW1 = nullptr;
    if (!side) {
        cudaStreamCreateWithFlags(&side, cudaStreamNonBlocking);
        cudaEventCreateWithFlags(&evFork, cudaEventDisableTiming);
        cudaEventCreateWithFlags(&evSide, cudaEventDisableTiming);
        cudaEventCreateWithFlags(&evW1,   cudaEventDisableTiming);
    }

    int blocks128 = (N + 127) / 128;
    int nb = (N + 255) / 256;
    int agg4_grid = (N + 15) / 16;
    int agg1_grid = (N + 7) / 8;
    int n4 = N * 64;

    // ---- fork side stream: W1 split first, then CSR etc. ----
    cudaEventRecord(evFork, 0);
    cudaStreamWaitEvent(side, evFork, 0);
    split_hi_kernel<<<(256 * 128 / 4 + 255) / 256, 256, 0, side>>>(
        (const float4*)W1, (__half2*)w1h, 256 * 128 / 4);
    cudaEventRecord(evW1, side);
    zero_stats2_kernel<<<1, 256, 0, side>>>(sumsA, sumsqA, sumsB, sumsqB);
    zero_int_kernel<<<nb, 256, 0, side>>>(counts, N);
    count_kernel<<<(EE + 255) / 256, 256, 0, side>>>(ei, E, N, counts);
    scan_block_kernel<<<nb, 256, 0, side>>>(counts, start, bsums, N);
    scan_sums_kernel<<<1, 256, 0, side>>>(bsums, nb);
    add_offsets_kernel<<<nb, 256, 0, side>>>(start, bsums, woff, N, EE);
    fill_kernel<<<(EE + 255) / 256, 256, 0, side>>>(ei, E, N, woff, csr_src);
    split_hi_kernel<<<(256 * 256 / 4 + 255) / 256, 256, 0, side>>>(
        (const float4*)W2, (__half2*)w2h, 256 * 256 / 4);
    split_hilo_kernel<<<(64 * 256 / 4 + 255) / 256, 256, 0, side>>>(
        (const float4*)W3, (__half2*)w3h, (__half2*)w3l, 64 * 256 / 4);
    cudaEventRecord(evSide, side);

    // ---- layer 1: K=128, 1-term, 128x256 tile ----
    split_hi_kernel<<<(N * 128 / 4 + 255) / 256, 256>>>(
        (const float4*)x, (__half2*)ah, N * 128 / 4);
    cudaStreamWaitEvent(0, evW1, 0);
    gemm_mma<256, 1><<<blocks128, 512, 61440>>>(ah, ah, w1h, w1h, h16, N, 128, 256,
                                                a1s, a1d, als, ald);
    cudaStreamWaitEvent(0, evSide, 0);
    agg4_kernel<<<agg4_grid, 256>>>(start, csr_src, als, ald, h16, b1, acc, N, sumsA, sumsqA);
    bn_split_kernel<<<(n4 + 255) / 256, 256>>>((const float4*)acc, nullptr,
        (const float4*)gamma, (const float4*)beta, (const float4*)sumsA, (const float4*)sumsqA,
        1.0f / (float)N, n4, (float4*)res, (__half2*)ah, nullptr);

    // ---- layer 2: K=256, 1-term, 128x256 tile ----
    gemm_mma<256, 1><<<blocks128, 512, 61440>>>(ah, ah, w2h, w2h, h16, N, 256, 256,
                                                a2s, a2d, als, ald);
    agg4_kernel<<<agg4_grid, 256>>>(start, csr_src, als, ald, h16, b2, acc, N, sumsB, sumsqB);
    bn_split_kernel<<<(n4 + 255) / 256, 256>>>((const float4*)acc, (const float4*)res,
        (const float4*)gamma, (const float4*)beta, (const float4*)sumsB, (const float4*)sumsqB,
        1.0f / (float)N, n4, nullptr, (__half2*)ah, (__half2*)al);

    // ---- layer 3: K=256, 3-term ----
    gemm_mma<64, 3><<<blocks128, 256, 61440>>>(ah, al, w3h, w3l, h16, N, 256, 64,
                                               a3s, a3d, als, ald);
    agg1_kernel<<<agg1_grid, 256>>>(start, csr_src, als, ald, h16, b3, out, N);
}